// round 3
// baseline (speedup 1.0000x reference)
#include <cuda_runtime.h>
#include <cstdint>

// Graph unpooling: out[dst] += edge_attr * x[src]
//   x:        [N_COARSE=50000, C=128] f32
//   src_idx:  [E=800000] int32 (JAX x64 disabled -> int64 request lowers to int32)
//   dst_idx:  [E=800000] int32
//   edge_attr:[E] f32
//   out:      [n_fine=200000, 128] f32

__global__ void _zero_kernel(float4* __restrict__ out, int n4) {
    int i = blockIdx.x * blockDim.x + threadIdx.x;
    if (i < n4) out[i] = make_float4(0.f, 0.f, 0.f, 0.f);
}

__global__ void __launch_bounds__(256)
_scatter_kernel(const float4* __restrict__ x4,
                const int* __restrict__ src,
                const int* __restrict__ dst,
                const float* __restrict__ attr,
                float* __restrict__ out,
                int E) {
    int gtid = blockIdx.x * blockDim.x + threadIdx.x;
    int e    = gtid >> 5;        // one warp per edge
    int lane = gtid & 31;        // lane handles 4 channels (float4)
    if (e >= E) return;

    int   s = __ldg(&src[e]);    // warp-uniform broadcast loads
    int   d = __ldg(&dst[e]);
    float w = __ldg(&attr[e]);

    // x row: 128 f32 = 32 float4; lane -> float4 slot
    float4 v = __ldg(&x4[(long long)s * 32 + lane]);
    v.x *= w; v.y *= w; v.z *= w; v.w *= w;

    float* p = out + (long long)d * 128 + (lane << 2);
    // Vector reduction (no return) — 1 L2 atomic transaction per 16B
    asm volatile("red.global.add.v4.f32 [%0], {%1, %2, %3, %4};"
                 :: "l"(p), "f"(v.x), "f"(v.y), "f"(v.z), "f"(v.w)
                 : "memory");
}

extern "C" void kernel_launch(void* const* d_in, const int* in_sizes, int n_in,
                              void* d_out, int out_size) {
    const float4* x4   = (const float4*)d_in[0];
    const int*    src  = (const int*)d_in[1];
    const int*    dst  = (const int*)d_in[2];
    const float*  attr = (const float*)d_in[3];
    float*        out  = (float*)d_out;

    int E  = in_sizes[1];
    int n4 = out_size / 4;   // out_size is a multiple of 4

    // Pass 1: zero the output (d_out is poisoned before timing)
    {
        int threads = 256;
        int blocks  = (n4 + threads - 1) / threads;
        _zero_kernel<<<blocks, threads>>>((float4*)out, n4);
    }

    // Pass 2: one warp per edge, red.v4.f32 scatter-add
    {
        int threads = 256;                       // 8 warps = 8 edges / block
        long long total_threads = (long long)E * 32;
        int blocks = (int)((total_threads + threads - 1) / threads);
        _scatter_kernel<<<blocks, threads>>>(x4, src, dst, attr, out, E);
    }
}

// round 4
// speedup vs baseline: 1.4365x; 1.4365x over previous
#include <cuda_runtime.h>
#include <cstdint>

// Graph unpooling: out[dst] += edge_attr * x[src]
//   x [50000,128] f32, src/dst [E=800000] i32, edge_attr [E] f32, out [200000,128] f32
// Strategy: build dst-CSR per call, then warp-per-node register accumulation.

#define MAXN 200704
#define MAXE 800000
#define SCAN_B 1024

__device__ int  g_count[MAXN];    // per-node edge count
__device__ int  g_incl[MAXN];     // within-block inclusive scan
__device__ int  g_start[MAXN];    // exclusive prefix = segment start
__device__ int  g_cursor[MAXN];   // running fill position
__device__ int  g_bsum[SCAN_B];   // per-block sums (inclusive-scanned in place)
__device__ int2 g_edges[MAXE];    // CSR payload: {src, bitcast(weight)}

__global__ void k_zero_counts(int n) {
    int i = blockIdx.x * blockDim.x + threadIdx.x;
    if (i < n) g_count[i] = 0;
}

__global__ void k_hist(const int* __restrict__ dst, int E) {
    int e = blockIdx.x * blockDim.x + threadIdx.x;
    if (e < E) atomicAdd(&g_count[dst[e]], 1);
}

// Per-block inclusive scan of g_count -> g_incl, block totals -> g_bsum
__global__ void __launch_bounds__(SCAN_B)
k_scan1(int n) {
    __shared__ int s[SCAN_B];
    int t = threadIdx.x, i = blockIdx.x * SCAN_B + t;
    int v = (i < n) ? g_count[i] : 0;
    s[t] = v; __syncthreads();
    #pragma unroll
    for (int off = 1; off < SCAN_B; off <<= 1) {
        int u = (t >= off) ? s[t - off] : 0;
        __syncthreads();
        s[t] += u;
        __syncthreads();
    }
    if (i < n) g_incl[i] = s[t];
    if (t == SCAN_B - 1) g_bsum[blockIdx.x] = s[t];
}

// Single block: inclusive scan of block sums (nb <= 1024)
__global__ void __launch_bounds__(SCAN_B)
k_scan2(int nb) {
    __shared__ int s[SCAN_B];
    int t = threadIdx.x;
    s[t] = (t < nb) ? g_bsum[t] : 0;
    __syncthreads();
    #pragma unroll
    for (int off = 1; off < SCAN_B; off <<= 1) {
        int u = (t >= off) ? s[t - off] : 0;
        __syncthreads();
        s[t] += u;
        __syncthreads();
    }
    if (t < nb) g_bsum[t] = s[t];
}

// start[i] = global exclusive prefix; cursor[i] = start[i]
__global__ void k_scan3(int n) {
    int i = blockIdx.x * blockDim.x + threadIdx.x;
    if (i >= n) return;
    int b = i / SCAN_B;
    int base = (b > 0) ? g_bsum[b - 1] : 0;
    int st = base + g_incl[i] - g_count[i];
    g_start[i]  = st;
    g_cursor[i] = st;
}

__global__ void k_fill(const int* __restrict__ src, const int* __restrict__ dst,
                       const float* __restrict__ attr, int E) {
    int e = blockIdx.x * blockDim.x + threadIdx.x;
    if (e >= E) return;
    int d = dst[e];
    int pos = atomicAdd(&g_cursor[d], 1);
    g_edges[pos] = make_int2(src[e], __float_as_int(attr[e]));
}

// One warp per fine node: register accumulate, single streaming store.
__global__ void __launch_bounds__(256)
k_gather(const float4* __restrict__ x4, float4* __restrict__ out4, int n) {
    int gtid = blockIdx.x * blockDim.x + threadIdx.x;
    int node = gtid >> 5;
    int lane = gtid & 31;
    if (node >= n) return;

    int beg = g_start[node];
    int cnt = g_count[node];

    float4 acc = make_float4(0.f, 0.f, 0.f, 0.f);
    int k = 0;
    // 2x unroll for memory-level parallelism
    for (; k + 1 < cnt; k += 2) {
        int2 e0 = __ldg(&g_edges[beg + k]);
        int2 e1 = __ldg(&g_edges[beg + k + 1]);
        float4 v0 = __ldg(&x4[(size_t)e0.x * 32 + lane]);
        float4 v1 = __ldg(&x4[(size_t)e1.x * 32 + lane]);
        float w0 = __int_as_float(e0.y);
        float w1 = __int_as_float(e1.y);
        acc.x += w0 * v0.x; acc.y += w0 * v0.y; acc.z += w0 * v0.z; acc.w += w0 * v0.w;
        acc.x += w1 * v1.x; acc.y += w1 * v1.y; acc.z += w1 * v1.z; acc.w += w1 * v1.w;
    }
    if (k < cnt) {
        int2 e0 = __ldg(&g_edges[beg + k]);
        float4 v0 = __ldg(&x4[(size_t)e0.x * 32 + lane]);
        float w0 = __int_as_float(e0.y);
        acc.x += w0 * v0.x; acc.y += w0 * v0.y; acc.z += w0 * v0.z; acc.w += w0 * v0.w;
    }
    // Streaming store: keep x resident in L2
    __stcs(&out4[(size_t)node * 32 + lane], acc);
}

extern "C" void kernel_launch(void* const* d_in, const int* in_sizes, int n_in,
                              void* d_out, int out_size) {
    const float4* x4   = (const float4*)d_in[0];
    const int*    src  = (const int*)d_in[1];
    const int*    dst  = (const int*)d_in[2];
    const float*  attr = (const float*)d_in[3];
    float4*       out4 = (float4*)d_out;

    int E = in_sizes[1];
    int n = out_size / 128;          // fine nodes (C=128)

    int tb = 256;
    int nb_scan = (n + SCAN_B - 1) / SCAN_B;

    k_zero_counts<<<(n + tb - 1) / tb, tb>>>(n);
    k_hist<<<(E + tb - 1) / tb, tb>>>(dst, E);
    k_scan1<<<nb_scan, SCAN_B>>>(n);
    k_scan2<<<1, SCAN_B>>>(nb_scan);
    k_scan3<<<(n + tb - 1) / tb, tb>>>(n);
    k_fill<<<(E + tb - 1) / tb, tb>>>(src, dst, attr, E);

    long long gather_threads = (long long)n * 32;
    k_gather<<<(int)((gather_threads + tb - 1) / tb), tb>>>(x4, out4, n);
}